// round 3
// baseline (speedup 1.0000x reference)
#include <cuda_runtime.h>

// Problem constants (fixed by the reference)
#define BB 1024
#define NN 16
#define TT 256
#define TPB 128                     // 128 threads = 64 (b,t) pairs x 2 ranks
#define TBLK 64                     // t-values per block
#define GRID (BB * (TT / TBLK))     // 4096 blocks, 4 per batch b

// Packed per-thread triangle storage: slot s (my s-th row, global row i=2s+rank)
// has capacity 2s+2 entries (k = 0..2s+1); offset s*s+s. Total 72 floats.
#define IDX(s, k) ((s) * (s) + (s) + (k))

// Scratch for deterministic single-launch reduction (no cudaMalloc allowed)
__device__ float g_partials[GRID];
__device__ unsigned int g_count = 0;   // self-resetting arrival counter

__global__ __launch_bounds__(TPB, 5) void gll_coop_kernel(
    const float* __restrict__ pred,
    const float* __restrict__ targ,
    const float* __restrict__ cov,
    float* __restrict__ out)
{
    const int tid  = threadIdx.x;
    const int rank = tid & 1;          // row-parity ownership
    const int tsub = tid >> 1;         // local t index
    const int lane = tid & 31;
    const int bid  = blockIdx.x;
    const int b    = bid >> 2;
    const int t    = ((bid & 3) << 6) + tsub;
    const unsigned FULL = 0xffffffffu;

    // cov plane (i,j) element t lives at cov[((b*16+i)*16+j)*256 + t]
    const float* covb = cov + ((size_t)b * NN * NN) * TT + t;

    float A[72];   // my rows' packed lower-triangle entries (+1 padding/row for rank0)
    float y[8];    // my rows' diff entries (forward-solve solution in place)

    // ---- Load phase: even lanes and odd lanes fetch different planes, each a
    // contiguous 16x4B=64B run over t -> fully coalesced sectors.
#pragma unroll
    for (int s = 0; s < 8; ++s) {
        const int i = 2 * s + rank;
        const int yoff = (b * NN + i) * TT + t;
        y[s] = pred[yoff] - targ[yoff];
#pragma unroll
        for (int j = 0; j <= 2 * s; ++j) {
            A[IDX(s, j)] = covb[(i * NN + j) * TT];
        }
        // last slot: real entry (2s+1,2s+1) for rank1; zeroed padding for rank0
        if (rank) A[IDX(s, 2 * s + 1)] = covb[(i * NN + 2 * s + 1) * TT];
        else      A[IDX(s, 2 * s + 1)] = 0.0f;
    }

    // ---- Fused Cholesky + forward solve, rows split across the rank pair.
    // Pivots >= 1 (Sigma = AA^T + I); pivot product <= ~1e14 fits fp32, so a
    // single __logf at the end replaces 16.
    float pivprod = 1.0f;
    float quad    = 0.0f;
#pragma unroll
    for (int j = 0; j < NN; ++j) {
        const int js = j >> 1, jr = j & 1;

        // pivot (j,j) owned by rank jr -> broadcast from owner lane of the pair
        float mypv = A[IDX(js, j)];
        float pv   = __shfl_sync(FULL, mypv, (lane & ~1) | jr);
        pivprod *= pv;
        const float invd = rsqrtf(pv);

        // scale column j in my rows (dead-row/padding slots scaled harmlessly)
#pragma unroll
        for (int s = js; s < 8; ++s) A[IDX(s, j)] *= invd;

        // y[j]: owner scales + accumulates quad; broadcast scaled value
        float yjs = y[js] * invd;
        float yj  = __shfl_sync(FULL, yjs, (lane & ~1) | jr);
        if (rank == jr) { y[js] = yj; quad = fmaf(yj, yj, quad); }

        // forward-solve update for my live rows i > j
#pragma unroll
        for (int s = js; s < 8; ++s) {
            if (2 * s + rank > j)            // folds to const except s==js, jr==0
                y[s] = fmaf(-A[IDX(s, j)], yj, y[s]);
        }

        // trailing update, k-outer so only one broadcast value is live at a time:
        // A[i][k] -= L[i][j] * L[k][j] for j < k <= i (padding writes harmless)
#pragma unroll
        for (int k = j + 1; k < NN; ++k) {
            const int ks = k >> 1, kr = k & 1;
            float myck = A[IDX(ks, j)];                       // owner's L[k][j]
            float ck   = __shfl_sync(FULL, myck, (lane & ~1) | kr);
#pragma unroll
            for (int s = ks; s < 8; ++s) {
                A[IDX(s, k)] = fmaf(-A[IDX(s, j)], ck, A[IDX(s, k)]);
            }
        }
    }

    // Each rank contributes its partial quad + half the logdet (pv identical on
    // both ranks, so 2 * 0.5 * log = log per (b,t)).
    float v = quad + 0.5f * __logf(pivprod);

    // ---- In-block reduction: warp shuffles + one smem pass over 4 warps
    const int wid = tid >> 5;
#pragma unroll
    for (int o = 16; o > 0; o >>= 1) v += __shfl_down_sync(FULL, v, o);

    __shared__ float warpsum[TPB / 32];
    __shared__ bool  isLast;
    if (lane == 0) warpsum[wid] = v;
    __syncthreads();

    if (tid == 0) {
        float s = warpsum[0] + warpsum[1] + warpsum[2] + warpsum[3];
        g_partials[bid] = s;
        __threadfence();
        unsigned int c = atomicAdd(&g_count, 1u);
        isLast = (c == (unsigned int)(GRID - 1));
    }
    __syncthreads();

    // Last arriving block performs the deterministic final sum (fixed order).
    if (isLast) {
        float s = 0.0f;
#pragma unroll 4
        for (int i = tid; i < GRID; i += TPB) s += g_partials[i];
#pragma unroll
        for (int o = 16; o > 0; o >>= 1) s += __shfl_down_sync(FULL, s, o);
        if (lane == 0) warpsum[wid] = s;
        __syncthreads();
        if (tid == 0) {
            float tot = warpsum[0] + warpsum[1] + warpsum[2] + warpsum[3];
            out[0] = tot * (1.0f / (float)(BB * TT));
            g_count = 0;   // reset for the next graph replay
        }
    }
}

extern "C" void kernel_launch(void* const* d_in, const int* in_sizes, int n_in,
                              void* d_out, int out_size)
{
    const float* pred = (const float*)d_in[0];   // prediction [B,N,T]
    const float* targ = (const float*)d_in[1];   // target     [B,N,T]
    const float* cov  = (const float*)d_in[2];   // cov        [B,N,N,T]
    float* out = (float*)d_out;

    gll_coop_kernel<<<GRID, TPB>>>(pred, targ, cov, out);
}